// round 3
// baseline (speedup 1.0000x reference)
#include <cuda_runtime.h>
#include <math.h>

#define WPB 6
#define PW 7956                     // floats per warp: Xs 1156 + Qs 1156 + Ks 1156 + Vs 2244 + Os 2244
#define TABF 1904                   // dmask 4*17*20 + sin 272 + cos 272
#define SMEMF (WPB*PW + TABF)

__device__ __forceinline__ float wsum(float v) {
#pragma unroll
    for (int d = 16; d > 0; d >>= 1) v += __shfl_xor_sync(0xffffffffu, v, d);
    return v;
}

__global__ void __launch_bounds__(192, 1) vit_kernel(
    const float* __restrict__ x,      const float* __restrict__ patch_w,
    const float* __restrict__ patch_b,const float* __restrict__ cls,
    const float* __restrict__ pos,
    const float* __restrict__ Wq, const float* __restrict__ Wk,
    const float* __restrict__ Wv, const float* __restrict__ Wg,
    const float* __restrict__ Wo,
    const float* __restrict__ ln1_s, const float* __restrict__ ln1_b,
    const float* __restrict__ w1, const float* __restrict__ b1,
    const float* __restrict__ w2, const float* __restrict__ b2,
    const float* __restrict__ ln2_s, const float* __restrict__ ln2_b,
    const float* __restrict__ lnf_s, const float* __restrict__ lnf_b,
    const float* __restrict__ neck_w, const float* __restrict__ neck_b,
    const float* __restrict__ head_w, const float* __restrict__ head_b,
    float* __restrict__ out, int nimg)
{
    extern __shared__ float sm[];
    const int tid = threadIdx.x;
    const int warp = tid >> 5, lane = tid & 31;

    float* wb = sm + warp * PW;
    float* Xs = wb;                 // [17][68]
    float* Qs = wb + 1156;          // [17][68]  (reused: Gs[17][132], Gf[17][12], neck)
    float* Ks = wb + 2312;          // [17][68]
    float* Vs = wb + 3468;          // [17][132]
    float* Os = wb + 5712;          // [17][132]
    float* tab = sm + WPB * PW;
    float* DM = tab;                // [4][17][20]  dmask * rsqrt(rowsum) * QH^-0.5
    float* SN = tab + 1360;         // [17][16]
    float* CS = tab + 1632;         // [17][16]

    // ---- per-CTA tables ----
    if (tid < 68) {
        int hh = tid / 17, n = tid % 17;
        float l0 = logf(1.0f / 32.0f), l1 = logf(1.0f / 512.0f);
        float gam = 1.0f - expf(l0 + (l1 - l0) * ((float)hh / 3.0f));
        float lg = logf(gam);
        float row[17]; float s = 0.f;
#pragma unroll
        for (int m = 0; m < 17; m++) {
            float v = (m <= n) ? expf(lg * (float)(n - m)) : 0.f;
            row[m] = v; s += v;
        }
        float nf = rsqrtf(s) * 0.25f;    // 0.25 = QH^-0.5 folded in
#pragma unroll
        for (int m = 0; m < 17; m++) DM[(hh * 17 + n) * 20 + m] = row[m] * nf;
    }
    for (int i = tid; i < 272; i += 192) {
        int t = i >> 4, j = i & 15;
        float e = (float)(j >> 1) / 7.0f;
        float ang = expf(-e * logf(10000.0f));
        float a = (float)t * ang;
        SN[i] = sinf(a); CS[i] = cosf(a);
    }
    __syncthreads();

    const int col = lane * 2;    // lane's 2 cols of D=64 tensors
    const int c4  = lane * 4;    // lane's 4 cols of V=128 tensors

    for (int img = blockIdx.x * WPB + warp; img < nimg; img += gridDim.x * WPB) {
        // ================= patch embed =================
        const float* xi = x + (long)img * 3072;
        for (int i = lane; i < 3072; i += 32) {
            int c = i >> 10, rem = i & 1023, yy = rem >> 5, xx = rem & 31;
            int p = ((yy >> 3) << 2) + (xx >> 3);
            int f = (c << 6) + ((yy & 7) << 3) + (xx & 7);
            wb[f * 16 + p] = xi[i];           // stage [192][16] (scratch over Xs/Qs/Ks)
        }
        __syncwarp();
        float2 h2[17];
        {
            float2 acc[16];
#pragma unroll
            for (int p = 0; p < 16; p++) acc[p] = make_float2(0.f, 0.f);
            for (int f = 0; f < 192; f++) {
                float2 w = *(const float2*)(patch_w + f * 64 + col);
                const float* st = wb + f * 16;
#pragma unroll
                for (int p = 0; p < 16; p++) {
                    float xv = st[p];
                    acc[p].x += xv * w.x; acc[p].y += xv * w.y;
                }
            }
            __syncwarp();
            float2 pb = *(const float2*)(patch_b + col);
            float2 cl = *(const float2*)(cls + col);
            float2 p0 = *(const float2*)(pos + col);
            h2[0] = make_float2(cl.x + p0.x, cl.y + p0.y);
#pragma unroll
            for (int t = 1; t < 17; t++) {
                float2 po = *(const float2*)(pos + t * 64 + col);
                h2[t] = make_float2(acc[t-1].x + pb.x + po.x,
                                    acc[t-1].y + pb.y + po.y);
            }
        }

        // ================= transformer layers =================
        for (int L = 0; L < 8; L++) {
            const float* wq = Wq + L * 4096;
            const float* wk = Wk + L * 4096;
            const float* wv = Wv + L * 8192;
            const float* wg = Wg + L * 8192;
            const float* wo = Wo + L * 8192;

            // ---- LN1 -> Xs ----
            {
                float2 ls = *(const float2*)(ln1_s + L * 64 + col);
                float2 lb = *(const float2*)(ln1_b + L * 64 + col);
#pragma unroll
                for (int t = 0; t < 17; t++) {
                    float s = wsum(h2[t].x + h2[t].y);
                    float q = wsum(h2[t].x * h2[t].x + h2[t].y * h2[t].y);
                    float mu = s * (1.0f / 64.0f);
                    float var = q * (1.0f / 64.0f) - mu * mu;
                    float r = rsqrtf(var + 1e-5f);
                    *(float2*)(Xs + t * 68 + col) =
                        make_float2((h2[t].x - mu) * r * ls.x + lb.x,
                                    (h2[t].y - mu) * r * ls.y + lb.y);
                }
            }
            __syncwarp();

            // ---- q,k = Xs @ Wq/Wk, rope, -> Qs,Ks ----
            {
                float2 qa[17], ka[17];
#pragma unroll
                for (int t = 0; t < 17; t++) { qa[t] = make_float2(0,0); ka[t] = make_float2(0,0); }
                for (int k0 = 0; k0 < 64; k0 += 4) {
                    float2 a0 = *(const float2*)(wq + (k0+0)*64 + col);
                    float2 a1 = *(const float2*)(wq + (k0+1)*64 + col);
                    float2 a2 = *(const float2*)(wq + (k0+2)*64 + col);
                    float2 a3 = *(const float2*)(wq + (k0+3)*64 + col);
                    float2 b0 = *(const float2*)(wk + (k0+0)*64 + col);
                    float2 b1 = *(const float2*)(wk + (k0+1)*64 + col);
                    float2 b2v= *(const float2*)(wk + (k0+2)*64 + col);
                    float2 b3 = *(const float2*)(wk + (k0+3)*64 + col);
#pragma unroll
                    for (int t = 0; t < 17; t++) {
                        float4 xv = *(const float4*)(Xs + t * 68 + k0);
                        qa[t].x += xv.x*a0.x + xv.y*a1.x + xv.z*a2.x + xv.w*a3.x;
                        qa[t].y += xv.x*a0.y + xv.y*a1.y + xv.z*a2.y + xv.w*a3.y;
                        ka[t].x += xv.x*b0.x + xv.y*b1.x + xv.z*b2v.x + xv.w*b3.x;
                        ka[t].y += xv.x*b0.y + xv.y*b1.y + xv.z*b2v.y + xv.w*b3.y;
                    }
                }
                int cc = col & 15;
#pragma unroll
                for (int t = 0; t < 17; t++) {
                    float sn = SN[t * 16 + cc], cn = CS[t * 16 + cc];
                    *(float2*)(Qs + t*68 + col) =
                        make_float2(qa[t].x*cn - qa[t].y*sn, qa[t].y*cn + qa[t].x*sn);
                    *(float2*)(Ks + t*68 + col) =
                        make_float2(ka[t].x*cn - ka[t].y*sn, ka[t].y*cn + ka[t].x*sn);
                }
            }

            // ---- v = Xs @ Wv -> Vs ----
            {
                float4 va[17];
#pragma unroll
                for (int t = 0; t < 17; t++) va[t] = make_float4(0,0,0,0);
                for (int k0 = 0; k0 < 64; k0 += 2) {
                    float4 v0 = *(const float4*)(wv + (k0+0)*128 + c4);
                    float4 v1 = *(const float4*)(wv + (k0+1)*128 + c4);
#pragma unroll
                    for (int t = 0; t < 17; t++) {
                        float2 xv = *(const float2*)(Xs + t * 68 + k0);
                        va[t].x += xv.x*v0.x + xv.y*v1.x;
                        va[t].y += xv.x*v0.y + xv.y*v1.y;
                        va[t].z += xv.x*v0.z + xv.y*v1.z;
                        va[t].w += xv.x*v0.w + xv.y*v1.w;
                    }
                }
#pragma unroll
                for (int t = 0; t < 17; t++) *(float4*)(Vs + t*132 + c4) = va[t];
            }
            __syncwarp();

            // ---- retention scores + o + per-head groupnorm -> Os ----
            for (int r = lane; r < 68; r += 32) {
                int hh = r & 3, n = r >> 2;
                const float* qp  = Qs + n * 68 + hh * 16;
                const float* dmr = DM + (hh * 17 + n) * 20;
                float ssum = 0.f;
                float ov[32];
#pragma unroll
                for (int j = 0; j < 32; j++) ov[j] = 0.f;
                for (int m = 0; m <= n; m++) {
                    const float* kp = Ks + m * 68 + hh * 16;
                    float s = 0.f;
#pragma unroll
                    for (int d = 0; d < 16; d++) s += qp[d] * kp[d];
                    s *= dmr[m];
                    ssum += s;
                    const float* vp = Vs + m * 132 + hh * 32;
#pragma unroll
                    for (int j = 0; j < 32; j++) ov[j] += s * vp[j];
                }
                float den = fabsf(ssum); den = den > 1.f ? den : 1.f;
                float inv = 1.f / den;
                float mu = 0.f, qq = 0.f;
#pragma unroll
                for (int j = 0; j < 32; j++) {
                    ov[j] *= inv;
                    mu += ov[j]; qq += ov[j] * ov[j];
                }
                mu *= (1.0f / 32.0f);
                float var = qq * (1.0f / 32.0f) - mu * mu;
                float rn = rsqrtf(var + 1e-5f);
                float* op = Os + n * 132 + hh * 32;
#pragma unroll
                for (int j = 0; j < 32; j++) op[j] = (ov[j] - mu) * rn;
            }
            __syncwarp();

            // ---- g = Xs @ Wg ; Gs = silu(g) * Os (overwrites Qs/Ks) ----
            {
                float4 ga[17];
#pragma unroll
                for (int t = 0; t < 17; t++) ga[t] = make_float4(0,0,0,0);
                for (int k0 = 0; k0 < 64; k0 += 2) {
                    float4 g0 = *(const float4*)(wg + (k0+0)*128 + c4);
                    float4 g1 = *(const float4*)(wg + (k0+1)*128 + c4);
#pragma unroll
                    for (int t = 0; t < 17; t++) {
                        float2 xv = *(const float2*)(Xs + t * 68 + k0);
                        ga[t].x += xv.x*g0.x + xv.y*g1.x;
                        ga[t].y += xv.x*g0.y + xv.y*g1.y;
                        ga[t].z += xv.x*g0.z + xv.y*g1.z;
                        ga[t].w += xv.x*g0.w + xv.y*g1.w;
                    }
                }
                float* Gs = Qs;
#pragma unroll
                for (int t = 0; t < 17; t++) {
                    float4 g = ga[t];
                    float4 o = *(const float4*)(Os + t * 132 + c4);
                    float4 rr;
                    rr.x = g.x / (1.f + expf(-g.x)) * o.x;
                    rr.y = g.y / (1.f + expf(-g.y)) * o.y;
                    rr.z = g.z / (1.f + expf(-g.z)) * o.z;
                    rr.w = g.w / (1.f + expf(-g.w)) * o.w;
                    *(float4*)(Gs + t * 132 + c4) = rr;
                }
            }
            __syncwarp();

            // ---- attn out = Gs @ Wo, residual ----
            {
                const float* Gs = Qs;
                float2 ao[17];
#pragma unroll
                for (int t = 0; t < 17; t++) ao[t] = make_float2(0,0);
                for (int k = 0; k < 128; k++) {
                    float2 w = *(const float2*)(wo + k * 64 + col);
#pragma unroll
                    for (int t = 0; t < 17; t++) {
                        float gv = Gs[t * 132 + k];
                        ao[t].x += gv * w.x; ao[t].y += gv * w.y;
                    }
                }
#pragma unroll
                for (int t = 0; t < 17; t++) { h2[t].x += ao[t].x; h2[t].y += ao[t].y; }
            }

            // ---- LN2 -> Xs ----
            {
                float2 ls = *(const float2*)(ln2_s + L * 64 + col);
                float2 lb = *(const float2*)(ln2_b + L * 64 + col);
#pragma unroll
                for (int t = 0; t < 17; t++) {
                    float s = wsum(h2[t].x + h2[t].y);
                    float q = wsum(h2[t].x * h2[t].x + h2[t].y * h2[t].y);
                    float mu = s * (1.0f / 64.0f);
                    float var = q * (1.0f / 64.0f) - mu * mu;
                    float r = rsqrtf(var + 1e-5f);
                    *(float2*)(Xs + t * 68 + col) =
                        make_float2((h2[t].x - mu) * r * ls.x + lb.x,
                                    (h2[t].y - mu) * r * ls.y + lb.y);
                }
            }
            __syncwarp();

            // ---- FFN: gelu(Xs @ w1 + b1) -> Gf ----
            {
                float* Gf = Qs;
                const float* pw1 = w1 + L * 768;
                const float* pb1 = b1 + L * 12;
                for (int r = lane; r < 204; r += 32) {
                    int t = r / 12, j = r - t * 12;
                    float s = pb1[j];
                    const float* xr = Xs + t * 68;
                    for (int k = 0; k < 64; k++) s += xr[k] * pw1[k * 12 + j];
                    float c = 0.7978845608028654f * (s + 0.044715f * s * s * s);
                    Gf[r] = 0.5f * s * (1.f + tanhf(c));
                }
            }
            __syncwarp();

            // ---- h += Gf @ w2 + b2 ----
            {
                const float* Gf = Qs;
                const float* pw2 = w2 + L * 768;
                float2 b2v = *(const float2*)(b2 + L * 64 + col);
                float2 wv2[12];
#pragma unroll
                for (int k = 0; k < 12; k++) wv2[k] = *(const float2*)(pw2 + k * 64 + col);
#pragma unroll
                for (int t = 0; t < 17; t++) {
                    float ax = b2v.x, ay = b2v.y;
#pragma unroll
                    for (int k = 0; k < 12; k++) {
                        float gv = Gf[t * 12 + k];
                        ax += gv * wv2[k].x; ay += gv * wv2[k].y;
                    }
                    h2[t].x += ax; h2[t].y += ay;
                }
            }
            __syncwarp();
        } // layers

        // ================= final LN (token 16) + neck + head =================
        {
            float2 hv = h2[16];
            float s = wsum(hv.x + hv.y);
            float q = wsum(hv.x * hv.x + hv.y * hv.y);
            float mu = s * (1.0f / 64.0f);
            float var = q * (1.0f / 64.0f) - mu * mu;
            float r = rsqrtf(var + 1e-5f);
            float2 ls = *(const float2*)(lnf_s + col);
            float2 lb = *(const float2*)(lnf_b + col);
            Xs[col]   = (hv.x - mu) * r * ls.x + lb.x;
            Xs[col+1] = (hv.y - mu) * r * ls.y + lb.y;
        }
        __syncwarp();
        if (lane < 16) {
            float s = neck_b[lane];
            for (int k = 0; k < 64; k++) s += Xs[k] * neck_w[k * 16 + lane];
            Qs[lane] = s;
        }
        __syncwarp();
        if (lane < 10) {
            float s = head_b[lane];
#pragma unroll
            for (int k = 0; k < 16; k++) s += Qs[k] * head_w[k * 10 + lane];
            out[(long)img * 10 + lane] = s;
        }
        __syncwarp();
    } // img loop
}

extern "C" void kernel_launch(void* const* d_in, const int* in_sizes, int n_in,
                              void* d_out, int out_size) {
    const float* x       = (const float*)d_in[0];
    const float* patch_w = (const float*)d_in[1];
    const float* patch_b = (const float*)d_in[2];
    const float* cls     = (const float*)d_in[3];
    const float* pos     = (const float*)d_in[4];
    const float* Wq      = (const float*)d_in[5];
    const float* Wk      = (const float*)d_in[6];
    const float* Wv      = (const float*)d_in[7];
    const float* Wg      = (const float*)d_in[8];
    const float* Wo      = (const float*)d_in[9];
    const float* ln1_s   = (const float*)d_in[10];
    const float* ln1_b   = (const float*)d_in[11];
    const float* w1      = (const float*)d_in[12];
    const float* b1      = (const float*)d_in[13];
    const float* w2      = (const float*)d_in[14];
    const float* b2      = (const float*)d_in[15];
    const float* ln2_s   = (const float*)d_in[16];
    const float* ln2_b   = (const float*)d_in[17];
    const float* lnf_s   = (const float*)d_in[18];
    const float* lnf_b   = (const float*)d_in[19];
    const float* neck_w  = (const float*)d_in[20];
    const float* neck_b  = (const float*)d_in[21];
    const float* head_w  = (const float*)d_in[22];
    const float* head_b  = (const float*)d_in[23];
    float* out = (float*)d_out;

    int nimg = in_sizes[0] / 3072;
    cudaFuncSetAttribute(vit_kernel, cudaFuncAttributeMaxDynamicSharedMemorySize,
                         SMEMF * (int)sizeof(float));
    int blocks = (nimg + WPB - 1) / WPB;
    if (blocks < 1) blocks = 1;
    vit_kernel<<<blocks, 192, SMEMF * sizeof(float)>>>(
        x, patch_w, patch_b, cls, pos, Wq, Wk, Wv, Wg, Wo,
        ln1_s, ln1_b, w1, b1, w2, b2, ln2_s, ln2_b, lnf_s, lnf_b,
        neck_w, neck_b, head_w, head_b, out, nimg);
}

// round 5
// speedup vs baseline: 1.3781x; 1.3781x over previous
#include <cuda_runtime.h>
#include <math.h>

#define WPB 8
#define PW 4692                     // floats/warp: Xs 1156 + Qs 1156 + Ks 1156 + S 1224
#define TABF 1904                   // dmask 4*17*20 + sin 272 + cos 272
#define SMEMF (WPB*PW + TABF)

__device__ __forceinline__ float wsum(float v) {
#pragma unroll
    for (int d = 16; d > 0; d >>= 1) v += __shfl_xor_sync(0xffffffffu, v, d);
    return v;
}

__global__ void __launch_bounds__(256, 1) vit_kernel(
    const float* __restrict__ x,      const float* __restrict__ patch_w,
    const float* __restrict__ patch_b,const float* __restrict__ cls,
    const float* __restrict__ pos,
    const float* __restrict__ Wq, const float* __restrict__ Wk,
    const float* __restrict__ Wv, const float* __restrict__ Wg,
    const float* __restrict__ Wo,
    const float* __restrict__ ln1_s, const float* __restrict__ ln1_b,
    const float* __restrict__ w1, const float* __restrict__ b1,
    const float* __restrict__ w2, const float* __restrict__ b2,
    const float* __restrict__ ln2_s, const float* __restrict__ ln2_b,
    const float* __restrict__ lnf_s, const float* __restrict__ lnf_b,
    const float* __restrict__ neck_w, const float* __restrict__ neck_b,
    const float* __restrict__ head_w, const float* __restrict__ head_b,
    float* __restrict__ out, int nimg)
{
    extern __shared__ float sm[];
    const int tid = threadIdx.x;
    const int warp = tid >> 5, lane = tid & 31;

    float* wb = sm + warp * PW;
    float* Xs = wb;                 // [17][68]
    float* Qs = wb + 1156;          // [17][68]  (reused: Gs[17][132], Gf, neck)
    float* Ks = wb + 2312;          // [17][68]
    float* Ssc= wb + 3468;          // [68][18]  normalized scores (dmask+den folded)
    float* tab = sm + WPB * PW;
    float* DM = tab;                // [4][17][20]  dmask * rsqrt(rowsum) * QH^-0.5
    float* SN = tab + 1360;         // [17][16]
    float* CS = tab + 1632;         // [17][16]

    // ---- per-CTA tables ----
    if (tid < 68) {
        int hh = tid / 17, n = tid % 17;
        float l0 = logf(1.0f / 32.0f), l1 = logf(1.0f / 512.0f);
        float gam = 1.0f - expf(l0 + (l1 - l0) * ((float)hh / 3.0f));
        float lg = logf(gam);
        float row[17]; float s = 0.f;
#pragma unroll
        for (int m = 0; m < 17; m++) {
            float v = (m <= n) ? expf(lg * (float)(n - m)) : 0.f;
            row[m] = v; s += v;
        }
        float nf = rsqrtf(s) * 0.25f;    // 0.25 = QH^-0.5 folded in
#pragma unroll
        for (int m = 0; m < 17; m++) DM[(hh * 17 + n) * 20 + m] = row[m] * nf;
    }
    for (int i = tid; i < 272; i += 256) {
        int t = i >> 4, j = i & 15;
        float e = (float)(j >> 1) / 7.0f;
        float ang = expf(-e * logf(10000.0f));
        float a = (float)t * ang;
        SN[i] = sinf(a); CS[i] = cosf(a);
    }
    __syncthreads();

    const int col = lane * 2;    // lane's 2 cols of D=64 tensors
    const int c4  = lane * 4;    // lane's 4 cols of V=128 tensors
    const int hh4 = lane >> 3;   // head owning cols c4..c4+3

    for (int img = blockIdx.x * WPB + warp; img < nimg; img += gridDim.x * WPB) {
        // ================= patch embed =================
        const float* xi = x + (long)img * 3072;
        for (int i = lane; i < 3072; i += 32) {
            int c = i >> 10, rem = i & 1023, yy = rem >> 5, xx = rem & 31;
            int p = ((yy >> 3) << 2) + (xx >> 3);
            int f = (c << 6) + ((yy & 7) << 3) + (xx & 7);
            wb[f * 16 + p] = xi[i];           // stage [192][16] over Xs/Qs/Ks
        }
        __syncwarp();
        float2 h2[17];
        {
            float2 acc[16];
#pragma unroll
            for (int p = 0; p < 16; p++) acc[p] = make_float2(0.f, 0.f);
#pragma unroll 1
            for (int f = 0; f < 192; f++) {
                float2 w = *(const float2*)(patch_w + f * 64 + col);
                const float* st = wb + f * 16;
#pragma unroll
                for (int p = 0; p < 16; p++) {
                    float xv = st[p];
                    acc[p].x += xv * w.x; acc[p].y += xv * w.y;
                }
            }
            __syncwarp();
            float2 pb = *(const float2*)(patch_b + col);
            float2 cl = *(const float2*)(cls + col);
            float2 p0 = *(const float2*)(pos + col);
            h2[0] = make_float2(cl.x + p0.x, cl.y + p0.y);
#pragma unroll
            for (int t = 1; t < 17; t++) {
                float2 po = *(const float2*)(pos + t * 64 + col);
                h2[t] = make_float2(acc[t-1].x + pb.x + po.x,
                                    acc[t-1].y + pb.y + po.y);
            }
        }

        // ================= transformer layers =================
#pragma unroll 1
        for (int L = 0; L < 8; L++) {
            const float* wq = Wq + L * 4096;
            const float* wk = Wk + L * 4096;
            const float* wv = Wv + L * 8192;
            const float* wg = Wg + L * 8192;
            const float* wo = Wo + L * 8192;

            // ---- LN1 -> Xs ----
            {
                float2 ls = *(const float2*)(ln1_s + L * 64 + col);
                float2 lb = *(const float2*)(ln1_b + L * 64 + col);
#pragma unroll
                for (int t = 0; t < 17; t++) {
                    float s = wsum(h2[t].x + h2[t].y);
                    float q = wsum(h2[t].x * h2[t].x + h2[t].y * h2[t].y);
                    float mu = s * (1.0f / 64.0f);
                    float var = q * (1.0f / 64.0f) - mu * mu;
                    float r = rsqrtf(var + 1e-5f);
                    *(float2*)(Xs + t * 68 + col) =
                        make_float2((h2[t].x - mu) * r * ls.x + lb.x,
                                    (h2[t].y - mu) * r * ls.y + lb.y);
                }
            }
            __syncwarp();

            // ---- q,k = Xs @ Wq/Wk, rope, -> Qs,Ks ----
            {
                float2 qa[17], ka[17];
#pragma unroll
                for (int t = 0; t < 17; t++) { qa[t] = make_float2(0,0); ka[t] = make_float2(0,0); }
#pragma unroll 1
                for (int k0 = 0; k0 < 64; k0 += 4) {
                    float2 a0 = *(const float2*)(wq + (k0+0)*64 + col);
                    float2 a1 = *(const float2*)(wq + (k0+1)*64 + col);
                    float2 a2 = *(const float2*)(wq + (k0+2)*64 + col);
                    float2 a3 = *(const float2*)(wq + (k0+3)*64 + col);
                    float2 b0 = *(const float2*)(wk + (k0+0)*64 + col);
                    float2 b1 = *(const float2*)(wk + (k0+1)*64 + col);
                    float2 b2v= *(const float2*)(wk + (k0+2)*64 + col);
                    float2 b3 = *(const float2*)(wk + (k0+3)*64 + col);
#pragma unroll
                    for (int t = 0; t < 17; t++) {
                        float4 xv = *(const float4*)(Xs + t * 68 + k0);
                        qa[t].x += xv.x*a0.x + xv.y*a1.x + xv.z*a2.x + xv.w*a3.x;
                        qa[t].y += xv.x*a0.y + xv.y*a1.y + xv.z*a2.y + xv.w*a3.y;
                        ka[t].x += xv.x*b0.x + xv.y*b1.x + xv.z*b2v.x + xv.w*b3.x;
                        ka[t].y += xv.x*b0.y + xv.y*b1.y + xv.z*b2v.y + xv.w*b3.y;
                    }
                }
                int cc = col & 15;
#pragma unroll
                for (int t = 0; t < 17; t++) {
                    float sn = SN[t * 16 + cc], cn = CS[t * 16 + cc];
                    *(float2*)(Qs + t*68 + col) =
                        make_float2(qa[t].x*cn - qa[t].y*sn, qa[t].y*cn + qa[t].x*sn);
                    *(float2*)(Ks + t*68 + col) =
                        make_float2(ka[t].x*cn - ka[t].y*sn, ka[t].y*cn + ka[t].x*sn);
                }
            }

            // ---- v = Xs @ Wv -> registers (4 cols/lane) ----
            float4 va[17];
            {
#pragma unroll
                for (int t = 0; t < 17; t++) va[t] = make_float4(0,0,0,0);
#pragma unroll 1
                for (int k0 = 0; k0 < 64; k0 += 2) {
                    float4 v0 = *(const float4*)(wv + (k0+0)*128 + c4);
                    float4 v1 = *(const float4*)(wv + (k0+1)*128 + c4);
#pragma unroll
                    for (int t = 0; t < 17; t++) {
                        float2 xv = *(const float2*)(Xs + t * 68 + k0);
                        va[t].x += xv.x*v0.x + xv.y*v1.x;
                        va[t].y += xv.x*v0.y + xv.y*v1.y;
                        va[t].z += xv.x*v0.z + xv.y*v1.z;
                        va[t].w += xv.x*v0.w + xv.y*v1.w;
                    }
                }
            }
            __syncwarp();

            // ---- stage A: normalized scores -> Ssc[68][18] ----
#pragma unroll 1
            for (int r = lane; r < 68; r += 32) {
                int hh = r & 3, n = r >> 2;
                const float* qp = Qs + n * 68 + hh * 16;
                float4 q0 = *(const float4*)(qp);
                float4 q1 = *(const float4*)(qp + 4);
                float4 q2 = *(const float4*)(qp + 8);
                float4 q3 = *(const float4*)(qp + 12);
                const float* dmr = DM + (hh * 17 + n) * 20;
                float sv[17]; float ssum = 0.f;
#pragma unroll
                for (int m = 0; m < 17; m++) {
                    if (m <= n) {
                        const float* kp = Ks + m * 68 + hh * 16;
                        float4 k0 = *(const float4*)(kp);
                        float4 k1 = *(const float4*)(kp + 4);
                        float4 k2 = *(const float4*)(kp + 8);
                        float4 k3 = *(const float4*)(kp + 12);
                        float s = q0.x*k0.x + q0.y*k0.y + q0.z*k0.z + q0.w*k0.w
                                + q1.x*k1.x + q1.y*k1.y + q1.z*k1.z + q1.w*k1.w
                                + q2.x*k2.x + q2.y*k2.y + q2.z*k2.z + q2.w*k2.w
                                + q3.x*k3.x + q3.y*k3.y + q3.z*k3.z + q3.w*k3.w;
                        s *= dmr[m];
                        sv[m] = s; ssum += s;
                    }
                }
                float den = fabsf(ssum); den = den > 1.f ? den : 1.f;
                float inv = 1.f / den;
                float* sp = Ssc + (hh * 17 + n) * 18;
#pragma unroll
                for (int m = 0; m < 17; m++) if (m <= n) sp[m] = sv[m] * inv;
            }
            __syncwarp();

            // ---- stage B: o = S @ v in registers + per-head groupnorm ----
            float4 ov[17];
            {
#pragma unroll
                for (int n = 0; n < 17; n++) ov[n] = make_float4(0,0,0,0);
                const float* Sb = Ssc + hh4 * 17 * 18;
#pragma unroll
                for (int m = 0; m < 17; m++) {
                    float4 vm = va[m];
#pragma unroll
                    for (int n = m; n < 17; n++) {
                        float sc = Sb[n * 18 + m];
                        ov[n].x += sc * vm.x; ov[n].y += sc * vm.y;
                        ov[n].z += sc * vm.z; ov[n].w += sc * vm.w;
                    }
                }
#pragma unroll
                for (int n = 0; n < 17; n++) {
                    float4 o = ov[n];
                    float pm = o.x + o.y + o.z + o.w;
                    float pq = o.x*o.x + o.y*o.y + o.z*o.z + o.w*o.w;
#pragma unroll
                    for (int d = 1; d < 8; d <<= 1) {
                        pm += __shfl_xor_sync(0xffffffffu, pm, d);
                        pq += __shfl_xor_sync(0xffffffffu, pq, d);
                    }
                    float mu = pm * (1.0f / 32.0f);
                    float var = pq * (1.0f / 32.0f) - mu * mu;
                    float rn = rsqrtf(var + 1e-5f);
                    ov[n].x = (o.x - mu) * rn; ov[n].y = (o.y - mu) * rn;
                    ov[n].z = (o.z - mu) * rn; ov[n].w = (o.w - mu) * rn;
                }
            }

            // ---- g = Xs @ Wg ; Gs = silu(g) * ov (overwrites Qs/Ks) ----
            {
                float4 ga[17];
#pragma unroll
                for (int t = 0; t < 17; t++) ga[t] = make_float4(0,0,0,0);
#pragma unroll 1
                for (int k0 = 0; k0 < 64; k0 += 2) {
                    float4 g0 = *(const float4*)(wg + (k0+0)*128 + c4);
                    float4 g1 = *(const float4*)(wg + (k0+1)*128 + c4);
#pragma unroll
                    for (int t = 0; t < 17; t++) {
                        float2 xv = *(const float2*)(Xs + t * 68 + k0);
                        ga[t].x += xv.x*g0.x + xv.y*g1.x;
                        ga[t].y += xv.x*g0.y + xv.y*g1.y;
                        ga[t].z += xv.x*g0.z + xv.y*g1.z;
                        ga[t].w += xv.x*g0.w + xv.y*g1.w;
                    }
                }
                float* Gs = Qs;
#pragma unroll
                for (int t = 0; t < 17; t++) {
                    float4 g = ga[t];
                    float4 o = ov[t];
                    float4 rr;
                    rr.x = g.x / (1.f + expf(-g.x)) * o.x;
                    rr.y = g.y / (1.f + expf(-g.y)) * o.y;
                    rr.z = g.z / (1.f + expf(-g.z)) * o.z;
                    rr.w = g.w / (1.f + expf(-g.w)) * o.w;
                    *(float4*)(Gs + t * 132 + c4) = rr;
                }
            }
            __syncwarp();

            // ---- attn out = Gs @ Wo (k vectorized by 4), residual ----
            {
                const float* Gs = Qs;
                float2 ao[17];
#pragma unroll
                for (int t = 0; t < 17; t++) ao[t] = make_float2(0,0);
#pragma unroll 1
                for (int k0 = 0; k0 < 128; k0 += 4) {
                    float2 w0 = *(const float2*)(wo + (k0+0)*64 + col);
                    float2 w1 = *(const float2*)(wo + (k0+1)*64 + col);
                    float2 w2 = *(const float2*)(wo + (k0+2)*64 + col);
                    float2 w3 = *(const float2*)(wo + (k0+3)*64 + col);
#pragma unroll
                    for (int t = 0; t < 17; t++) {
                        float4 gv = *(const float4*)(Gs + t * 132 + k0);
                        ao[t].x += gv.x*w0.x + gv.y*w1.x + gv.z*w2.x + gv.w*w3.x;
                        ao[t].y += gv.x*w0.y + gv.y*w1.y + gv.z*w2.y + gv.w*w3.y;
                    }
                }
#pragma unroll
                for (int t = 0; t < 17; t++) { h2[t].x += ao[t].x; h2[t].y += ao[t].y; }
            }

            // ---- LN2 -> Xs ----
            {
                float2 ls = *(const float2*)(ln2_s + L * 64 + col);
                float2 lb = *(const float2*)(ln2_b + L * 64 + col);
#pragma unroll
                for (int t = 0; t < 17; t++) {
                    float s = wsum(h2[t].x + h2[t].y);
                    float q = wsum(h2[t].x * h2[t].x + h2[t].y * h2[t].y);
                    float mu = s * (1.0f / 64.0f);
                    float var = q * (1.0f / 64.0f) - mu * mu;
                    float r = rsqrtf(var + 1e-5f);
                    *(float2*)(Xs + t * 68 + col) =
                        make_float2((h2[t].x - mu) * r * ls.x + lb.x,
                                    (h2[t].y - mu) * r * ls.y + lb.y);
                }
            }
            __syncwarp();

            // ---- FFN: gelu(Xs @ w1 + b1) -> Gf ----
            {
                float* Gf = Qs;
                const float* pw1 = w1 + L * 768;
                const float* pb1 = b1 + L * 12;
#pragma unroll 1
                for (int r = lane; r < 204; r += 32) {
                    int t = r / 12, j = r - t * 12;
                    float s = pb1[j];
                    const float* xr = Xs + t * 68;
#pragma unroll
                    for (int k4 = 0; k4 < 64; k4 += 4) {
                        float4 xv = *(const float4*)(xr + k4);
                        s += xv.x * pw1[(k4+0)*12 + j] + xv.y * pw1[(k4+1)*12 + j]
                           + xv.z * pw1[(k4+2)*12 + j] + xv.w * pw1[(k4+3)*12 + j];
                    }
                    float c = 0.7978845608028654f * (s + 0.044715f * s * s * s);
                    Gf[r] = 0.5f * s * (1.f + tanhf(c));
                }
            }
            __syncwarp();

            // ---- h += Gf @ w2 + b2 ----
            {
                const float* Gf = Qs;
                const float* pw2 = w2 + L * 768;
                float2 b2v = *(const float2*)(b2 + L * 64 + col);
                float2 wv2[12];
#pragma unroll
                for (int k = 0; k < 12; k++) wv2[k] = *(const float2*)(pw2 + k * 64 + col);
#pragma unroll
                for (int t = 0; t < 17; t++) {
                    float ax = b2v.x, ay = b2v.y;
#pragma unroll
                    for (int k = 0; k < 12; k++) {
                        float gv = Gf[t * 12 + k];
                        ax += gv * wv2[k].x; ay += gv * wv2[k].y;
                    }
                    h2[t].x += ax; h2[t].y += ay;
                }
            }
            __syncwarp();
        } // layers

        // ================= final LN (token 16) + neck + head =================
        {
            float2 hv = h2[16];
            float s = wsum(hv.x + hv.y);
            float q = wsum(hv.x * hv.x + hv.y * hv.y);
            float mu = s * (1.0f / 64.0f);
            float var = q * (1.0f / 64.0f) - mu * mu;
            float r = rsqrtf(var + 1e-5f);
            float2 ls = *(const float2*)(lnf_s + col);
            float2 lb = *(const float2*)(lnf_b + col);
            Xs[col]   = (hv.x - mu) * r * ls.x + lb.x;
            Xs[col+1] = (hv.y - mu) * r * ls.y + lb.y;
        }
        __syncwarp();
        if (lane < 16) {
            float s = neck_b[lane];
#pragma unroll
            for (int k = 0; k < 64; k++) s += Xs[k] * neck_w[k * 16 + lane];
            Qs[lane] = s;
        }
        __syncwarp();
        if (lane < 10) {
            float s = head_b[lane];
#pragma unroll
            for (int k = 0; k < 16; k++) s += Qs[k] * head_w[k * 10 + lane];
            out[(long)img * 10 + lane] = s;
        }
        __syncwarp();
    } // img loop
}

extern "C" void kernel_launch(void* const* d_in, const int* in_sizes, int n_in,
                              void* d_out, int out_size) {
    const float* x       = (const float*)d_in[0];
    const float* patch_w = (const float*)d_in[1];
    const float* patch_b = (const float*)d_in[2];
    const float* cls     = (const float*)d_in[3];
    const float* pos     = (const float*)d_in[4];
    const float* Wq      = (const float*)d_in[5];
    const float* Wk      = (const float*)d_in[6];
    const float* Wv      = (const float*)d_in[7];
    const float* Wg      = (const float*)d_in[8];
    const float* Wo      = (const float*)d_in[9];
    const float* ln1_s   = (const float*)d_in[10];
    const float* ln1_b   = (const float*)d_in[11];
    const float* w1      = (const float*)d_in[12];
    const float* b1      = (const float*)d_in[13];
    const float* w2      = (const float*)d_in[14];
    const float* b2      = (const float*)d_in[15];
    const float* ln2_s   = (const float*)d_in[16];
    const float* ln2_b   = (const float*)d_in[17];
    const float* lnf_s   = (const float*)d_in[18];
    const float* lnf_b   = (const float*)d_in[19];
    const float* neck_w  = (const float*)d_in[20];
    const float* neck_b  = (const float*)d_in[21];
    const float* head_w  = (const float*)d_in[22];
    const float* head_b  = (const float*)d_in[23];
    float* out = (float*)d_out;

    int nimg = in_sizes[0] / 3072;
    cudaFuncSetAttribute(vit_kernel, cudaFuncAttributeMaxDynamicSharedMemorySize,
                         SMEMF * (int)sizeof(float));
    int blocks = (nimg + WPB - 1) / WPB;
    if (blocks < 1) blocks = 1;
    vit_kernel<<<blocks, 256, SMEMF * sizeof(float)>>>(
        x, patch_w, patch_b, cls, pos, Wq, Wk, Wv, Wg, Wo,
        ln1_s, ln1_b, w1, b1, w2, b2, ln2_s, ln2_b, lnf_s, lnf_b,
        neck_w, neck_b, head_w, head_b, out, nimg);
}